// round 1
// baseline (speedup 1.0000x reference)
#include <cuda_runtime.h>
#include <math.h>

// Problem constants
#define TOK     4096      // B*S tokens
#define DMODEL  1024
#define DHID    4096
#define NHEADS  16
#define DHEAD   64
#define SEQLEN  2048

// Scratch (allocation-free: __device__ globals)
__device__ float g_Q[TOK * DMODEL];
__device__ float g_K[TOK * DMODEL];
__device__ float g_V[TOK * DMODEL];
__device__ float g_ctx[TOK * DMODEL];
__device__ float g_x1[TOK * DMODEL];
__device__ float g_h[TOK * DHID];     // also used as [TOK, DMODEL] temp for Wo output

// ---------------------------------------------------------------------------
// Generic tiled GEMM: C[M,N] = A[M,K] @ W[K,N] (+bias) (+gelu)
// 64x64 block tile, BK=16, 256 threads, 4x4 microtile per thread.
// EPI: 0 = none, 1 = +bias, 2 = +bias then exact GELU
// ---------------------------------------------------------------------------
template <int EPI>
__global__ __launch_bounds__(256) void gemm_kernel(
    const float* __restrict__ A, const float* __restrict__ W,
    const float* __restrict__ bias, float* __restrict__ C,
    int M, int K, int N)
{
    __shared__ float sA[16][68];   // transposed: sA[k][row], padded
    __shared__ float sB[16][64];   // natural:    sB[k][col]

    const int t  = threadIdx.x;
    const int tx = t & 15;
    const int ty = t >> 4;
    const int rowBase = blockIdx.y << 6;
    const int colBase = blockIdx.x << 6;

    // A-tile load mapping: 256 threads x float4 = 1024 elems (64 rows x 16 k)
    const int arow = t >> 2;
    const int ak   = (t & 3) << 2;
    // B-tile load mapping: 16 k-rows x 64 cols
    const int bk   = t >> 4;
    const int bcol = (t & 15) << 2;

    const float* Ap = A + (size_t)(rowBase + arow) * K + ak;
    const float* Wp = W + (size_t)bk * N + colBase + bcol;

    float acc[4][4] = {};

    for (int k0 = 0; k0 < K; k0 += 16) {
        float4 av = *(const float4*)(Ap + k0);
        sA[ak + 0][arow] = av.x;
        sA[ak + 1][arow] = av.y;
        sA[ak + 2][arow] = av.z;
        sA[ak + 3][arow] = av.w;
        *(float4*)&sB[bk][bcol] = *(const float4*)(Wp + (size_t)k0 * N);
        __syncthreads();

#pragma unroll
        for (int k = 0; k < 16; k++) {
            float4 a4 = *(const float4*)&sA[k][ty << 2];
            float4 b4 = *(const float4*)&sB[k][tx << 2];
            float ar[4] = {a4.x, a4.y, a4.z, a4.w};
            float br[4] = {b4.x, b4.y, b4.z, b4.w};
#pragma unroll
            for (int i = 0; i < 4; i++)
#pragma unroll
                for (int j = 0; j < 4; j++)
                    acc[i][j] = fmaf(ar[i], br[j], acc[i][j]);
        }
        __syncthreads();
    }

    const int row = rowBase + (ty << 2);
    const int col = colBase + (tx << 2);
    float4 bb = make_float4(0.f, 0.f, 0.f, 0.f);
    if (EPI >= 1) bb = *(const float4*)(bias + col);

#pragma unroll
    for (int i = 0; i < 4; i++) {
        float4 v;
        v.x = acc[i][0]; v.y = acc[i][1]; v.z = acc[i][2]; v.w = acc[i][3];
        if (EPI >= 1) { v.x += bb.x; v.y += bb.y; v.z += bb.z; v.w += bb.w; }
        if (EPI == 2) {
            v.x = 0.5f * v.x * (1.0f + erff(v.x * 0.7071067811865475f));
            v.y = 0.5f * v.y * (1.0f + erff(v.y * 0.7071067811865475f));
            v.z = 0.5f * v.z * (1.0f + erff(v.z * 0.7071067811865475f));
            v.w = 0.5f * v.w * (1.0f + erff(v.w * 0.7071067811865475f));
        }
        *(float4*)(C + (size_t)(row + i) * N + col) = v;
    }
}

// ---------------------------------------------------------------------------
// Causal flash attention.
// Grid: (S/64, H, B). Block: 256 threads = 16x16, 4x4 microtiles.
// Q/K/V layout: [tok, H*64] (head-interleaved), fp32.
// Smem: sQt (d-major Q), sKt (d-major K, reused as P^T), sV (key-major V).
// Exactly 48 KB static shared.
// ---------------------------------------------------------------------------
__global__ __launch_bounds__(256) void attn_kernel(
    const float* __restrict__ Q, const float* __restrict__ K,
    const float* __restrict__ V, float* __restrict__ O)
{
    __shared__ float sQt[64][64];   // sQt[d][row], pre-scaled by 1/sqrt(64)
    __shared__ float sKt[64][64];   // sKt[d][key]; reused as P^T[key][row]
    __shared__ float sV[64][64];    // sV[key][d]

    const int qb = blockIdx.x;
    const int h  = blockIdx.y;
    const int b  = blockIdx.z;
    const int t  = threadIdx.x;
    const int tx = t & 15;
    const int ty = t >> 4;
    const int q0 = qb << 6;

    // cooperative loader mapping: 4 threads per row, 16 floats each
    const int lr = t >> 2;          // row/key within 64-tile
    const int ld = (t & 3) << 4;    // d base (16 floats)

    // Load Q tile (transposed, pre-scaled)
    {
        const float* qg = Q + (size_t)(b * SEQLEN + q0 + lr) * DMODEL + h * DHEAD + ld;
#pragma unroll
        for (int u = 0; u < 4; u++) {
            float4 v4 = *(const float4*)(qg + u * 4);
            sQt[ld + u * 4 + 0][lr] = v4.x * 0.125f;
            sQt[ld + u * 4 + 1][lr] = v4.y * 0.125f;
            sQt[ld + u * 4 + 2][lr] = v4.z * 0.125f;
            sQt[ld + u * 4 + 3][lr] = v4.w * 0.125f;
        }
    }

    float m[4], l[4], o[4][4];
#pragma unroll
    for (int i = 0; i < 4; i++) {
        m[i] = -1e30f;
        l[i] = 0.f;
#pragma unroll
        for (int j = 0; j < 4; j++) o[i][j] = 0.f;
    }

    for (int jb = 0; jb <= qb; jb++) {
        __syncthreads();   // prev iteration done reading sKt/sV; also covers Q-load on iter 0
        const int j0 = jb << 6;
        {
            const float* kg = K + (size_t)(b * SEQLEN + j0 + lr) * DMODEL + h * DHEAD + ld;
            const float* vg = V + (size_t)(b * SEQLEN + j0 + lr) * DMODEL + h * DHEAD + ld;
#pragma unroll
            for (int u = 0; u < 4; u++) {
                float4 kv = *(const float4*)(kg + u * 4);
                sKt[ld + u * 4 + 0][lr] = kv.x;
                sKt[ld + u * 4 + 1][lr] = kv.y;
                sKt[ld + u * 4 + 2][lr] = kv.z;
                sKt[ld + u * 4 + 3][lr] = kv.w;
                *(float4*)&sV[lr][ld + u * 4] = *(const float4*)(vg + u * 4);
            }
        }
        __syncthreads();

        // S = Q K^T (scaled)
        float s[4][4] = {};
#pragma unroll 8
        for (int d = 0; d < 64; d++) {
            float4 a4 = *(const float4*)&sQt[d][ty << 2];
            float4 b4 = *(const float4*)&sKt[d][tx << 2];
            float ar[4] = {a4.x, a4.y, a4.z, a4.w};
            float br[4] = {b4.x, b4.y, b4.z, b4.w};
#pragma unroll
            for (int i = 0; i < 4; i++)
#pragma unroll
                for (int j = 0; j < 4; j++)
                    s[i][j] = fmaf(ar[i], br[j], s[i][j]);
        }

        // Causal mask (only diagonal block needs it; j0 == q0 there)
        if (jb == qb) {
#pragma unroll
            for (int i = 0; i < 4; i++)
#pragma unroll
                for (int j = 0; j < 4; j++)
                    if ((tx << 2) + j > (ty << 2) + i) s[i][j] = -1e30f;
        }

        // Online softmax update
        float newm[4], rsum[4], scale[4];
#pragma unroll
        for (int i = 0; i < 4; i++) {
            float rm = fmaxf(fmaxf(s[i][0], s[i][1]), fmaxf(s[i][2], s[i][3]));
#pragma unroll
            for (int off = 8; off; off >>= 1)
                rm = fmaxf(rm, __shfl_xor_sync(0xffffffffu, rm, off));
            newm[i] = fmaxf(m[i], rm);
            float rs = 0.f;
#pragma unroll
            for (int j = 0; j < 4; j++) {
                s[i][j] = __expf(s[i][j] - newm[i]);
                rs += s[i][j];
            }
#pragma unroll
            for (int off = 8; off; off >>= 1)
                rs += __shfl_xor_sync(0xffffffffu, rs, off);
            rsum[i]  = rs;
            scale[i] = __expf(m[i] - newm[i]);
            l[i] = l[i] * scale[i] + rsum[i];
            m[i] = newm[i];
#pragma unroll
            for (int j = 0; j < 4; j++) o[i][j] *= scale[i];
        }

        __syncthreads();   // everyone finished reading sKt before P^T overwrite

        // Write P^T into sKt's storage: sPt[key][row]
#pragma unroll
        for (int i = 0; i < 4; i++)
#pragma unroll
            for (int j = 0; j < 4; j++)
                sKt[(tx << 2) + j][(ty << 2) + i] = s[i][j];
        __syncthreads();

        // O += P V
#pragma unroll 8
        for (int kk = 0; kk < 64; kk++) {
            float4 a4 = *(const float4*)&sKt[kk][ty << 2];   // P^T rows
            float4 b4 = *(const float4*)&sV[kk][tx << 2];
            float ar[4] = {a4.x, a4.y, a4.z, a4.w};
            float br[4] = {b4.x, b4.y, b4.z, b4.w};
#pragma unroll
            for (int i = 0; i < 4; i++)
#pragma unroll
                for (int j = 0; j < 4; j++)
                    o[i][j] = fmaf(ar[i], br[j], o[i][j]);
        }
    }

    // Write context: O[tok, h*64 + d]
#pragma unroll
    for (int i = 0; i < 4; i++) {
        float inv = 1.0f / l[i];
        float* og = O + (size_t)(b * SEQLEN + q0 + (ty << 2) + i) * DMODEL + h * DHEAD + (tx << 2);
        float4 v;
        v.x = o[i][0] * inv; v.y = o[i][1] * inv; v.z = o[i][2] * inv; v.w = o[i][3] * inv;
        *(float4*)og = v;
    }
}

// ---------------------------------------------------------------------------
// out[row] = xres[row] + LayerNorm(t[row]) * g + b   (one block per token row)
// ---------------------------------------------------------------------------
__global__ __launch_bounds__(256) void ln_res_kernel(
    const float* __restrict__ xres, const float* __restrict__ tin,
    const float* __restrict__ gam, const float* __restrict__ bet,
    float* __restrict__ out)
{
    const int row = blockIdx.x;
    const int tid = threadIdx.x;
    const float* tr = tin + (size_t)row * DMODEL;

    __shared__ float red[256];
    __shared__ float s_mu, s_rstd;

    float sum = 0.f, sq = 0.f;
    for (int c = tid; c < DMODEL; c += 256) {
        float v = tr[c];
        sum += v;
        sq  += v * v;
    }
    red[tid] = sum;
    __syncthreads();
    for (int s = 128; s > 0; s >>= 1) {
        if (tid < s) red[tid] += red[tid + s];
        __syncthreads();
    }
    if (tid == 0) s_mu = red[0] * (1.0f / DMODEL);
    __syncthreads();
    red[tid] = sq;
    __syncthreads();
    for (int s = 128; s > 0; s >>= 1) {
        if (tid < s) red[tid] += red[tid + s];
        __syncthreads();
    }
    if (tid == 0) {
        float mu  = s_mu;
        float var = red[0] * (1.0f / DMODEL) - mu * mu;
        s_rstd = rsqrtf(var + 1e-5f);
    }
    __syncthreads();

    const float mu = s_mu, rstd = s_rstd;
    for (int c = tid; c < DMODEL; c += 256) {
        out[(size_t)row * DMODEL + c] =
            xres[(size_t)row * DMODEL + c] + (tr[c] - mu) * rstd * gam[c] + bet[c];
    }
}

// ---------------------------------------------------------------------------
extern "C" void kernel_launch(void* const* d_in, const int* in_sizes, int n_in,
                              void* d_out, int out_size)
{
    const float* x    = (const float*)d_in[0];
    const float* wq   = (const float*)d_in[1];
    const float* bq   = (const float*)d_in[2];
    const float* wk   = (const float*)d_in[3];
    const float* bk   = (const float*)d_in[4];
    const float* wv   = (const float*)d_in[5];
    const float* bv   = (const float*)d_in[6];
    const float* wo   = (const float*)d_in[7];
    const float* ln1g = (const float*)d_in[8];
    const float* ln1b = (const float*)d_in[9];
    const float* w1   = (const float*)d_in[10];
    const float* b1   = (const float*)d_in[11];
    const float* w2   = (const float*)d_in[12];
    const float* ln2g = (const float*)d_in[13];
    const float* ln2b = (const float*)d_in[14];
    float* out = (float*)d_out;

    void *pQ, *pK, *pV, *pCtx, *pX1, *pH;
    cudaGetSymbolAddress(&pQ,   g_Q);
    cudaGetSymbolAddress(&pK,   g_K);
    cudaGetSymbolAddress(&pV,   g_V);
    cudaGetSymbolAddress(&pCtx, g_ctx);
    cudaGetSymbolAddress(&pX1,  g_x1);
    cudaGetSymbolAddress(&pH,   g_h);
    float* Q   = (float*)pQ;
    float* Kc  = (float*)pK;
    float* V   = (float*)pV;
    float* ctx = (float*)pCtx;
    float* x1  = (float*)pX1;
    float* h   = (float*)pH;

    const dim3 thr(256);

    // 1) QKV projections
    gemm_kernel<1><<<dim3(16, 64), thr>>>(x, wq, bq, Q,  TOK, DMODEL, DMODEL);
    gemm_kernel<1><<<dim3(16, 64), thr>>>(x, wk, bk, Kc, TOK, DMODEL, DMODEL);
    gemm_kernel<1><<<dim3(16, 64), thr>>>(x, wv, bv, V,  TOK, DMODEL, DMODEL);

    // 2) Causal flash attention -> ctx [tok, H*64]
    attn_kernel<<<dim3(SEQLEN / 64, NHEADS, 2), thr>>>(Q, Kc, V, ctx);

    // 3) Output projection (no bias) -> h (as [TOK, DMODEL] temp)
    gemm_kernel<0><<<dim3(16, 64), thr>>>(ctx, wo, nullptr, h, TOK, DMODEL, DMODEL);

    // 4) x1 = x + LN1(h)
    ln_res_kernel<<<TOK, thr>>>(x, h, ln1g, ln1b, x1);

    // 5) h = gelu(x1 @ w1 + b1)  [TOK, DHID]
    gemm_kernel<2><<<dim3(64, 64), thr>>>(x1, w1, b1, h, TOK, DMODEL, DHID);

    // 6) ctx = h @ w2  [TOK, DMODEL]
    gemm_kernel<0><<<dim3(16, 64), thr>>>(h, w2, nullptr, ctx, TOK, DHID, DMODEL);

    // 7) out = x1 + LN2(ctx)
    ln_res_kernel<<<TOK, thr>>>(x1, ctx, ln2g, ln2b, out);
}

// round 2
// speedup vs baseline: 1.5267x; 1.5267x over previous
#include <cuda_runtime.h>
#include <cuda_bf16.h>
#include <math.h>
#include <stdint.h>

// Problem constants
#define TOK     4096      // B*S tokens
#define DMODEL  1024
#define DHID    4096
#define NHEADS  16
#define DHEAD   64
#define SEQLEN  2048

// Scratch (allocation-free: __device__ globals)
__device__ float g_Q[TOK * DMODEL];
__device__ float g_K[TOK * DMODEL];
__device__ float g_V[TOK * DMODEL];
__device__ float g_ctx[TOK * DMODEL];
__device__ float g_x1[TOK * DMODEL];
__device__ float g_h[TOK * DHID];

// ---------------------------------------------------------------------------
// bf16x3 split-precision tensor-core GEMM.
// C[M,N] = A[M,K] @ W[K,N] (+bias) (+gelu), fp32 in/out, fp32 accumulate.
// Each fp32 value is split v = hi + lo (both bf16); product uses 3 MMAs:
// hi*hi + hi*lo + lo*hi  (error ~2^-17, ~fp32-class for this tolerance).
// CTA tile 128x128, BK=32, 256 threads = 8 warps in 2x4, warp tile 64x32.
// ---------------------------------------------------------------------------
#define APAD 40    // smem A row stride in bf16 elems (32 + 8) -> conflict-free LDSM
#define BPAD 136   // smem B row stride in bf16 elems (128 + 8)

__device__ __forceinline__ uint32_t smem_u32(const void* p) {
    return (uint32_t)__cvta_generic_to_shared(p);
}
__device__ __forceinline__ void ldsm_x4(uint32_t* r, uint32_t a) {
    asm volatile("ldmatrix.sync.aligned.m8n8.x4.shared.b16 {%0,%1,%2,%3},[%4];\n"
                 : "=r"(r[0]), "=r"(r[1]), "=r"(r[2]), "=r"(r[3]) : "r"(a));
}
__device__ __forceinline__ void ldsm_x4t(uint32_t* r, uint32_t a) {
    asm volatile("ldmatrix.sync.aligned.m8n8.x4.trans.shared.b16 {%0,%1,%2,%3},[%4];\n"
                 : "=r"(r[0]), "=r"(r[1]), "=r"(r[2]), "=r"(r[3]) : "r"(a));
}
__device__ __forceinline__ void mma16816(float* d, const uint32_t* a, uint32_t b0, uint32_t b1) {
    asm volatile("mma.sync.aligned.m16n8k16.row.col.f32.bf16.bf16.f32 "
                 "{%0,%1,%2,%3},{%4,%5,%6,%7},{%8,%9},{%0,%1,%2,%3};\n"
                 : "+f"(d[0]), "+f"(d[1]), "+f"(d[2]), "+f"(d[3])
                 : "r"(a[0]), "r"(a[1]), "r"(a[2]), "r"(a[3]), "r"(b0), "r"(b1));
}

__device__ __forceinline__ void split4(float4 v, uint32_t* ph, uint32_t* pl) {
    // hi = bf16_rn(v), lo = bf16_rn(v - hi); pack 4 each into 2x uint32
    float f[4] = {v.x, v.y, v.z, v.w};
    unsigned short h[4], l[4];
#pragma unroll
    for (int i = 0; i < 4; i++) {
        __nv_bfloat16 bh = __float2bfloat16(f[i]);
        float r = f[i] - __bfloat162float(bh);
        __nv_bfloat16 bl = __float2bfloat16(r);
        h[i] = __bfloat16_as_ushort(bh);
        l[i] = __bfloat16_as_ushort(bl);
    }
    ph[0] = (uint32_t)h[0] | ((uint32_t)h[1] << 16);
    ph[1] = (uint32_t)h[2] | ((uint32_t)h[3] << 16);
    pl[0] = (uint32_t)l[0] | ((uint32_t)l[1] << 16);
    pl[1] = (uint32_t)l[2] | ((uint32_t)l[3] << 16);
}

// EPI: 0 = none, 1 = +bias, 2 = +bias then exact GELU
template <int EPI>
__global__ __launch_bounds__(256) void gemm_bf16x3(
    const float* __restrict__ A, const float* __restrict__ W,
    const float* __restrict__ bias, float* __restrict__ C,
    int M, int K, int N)
{
    __shared__ unsigned short sAh[128 * APAD];
    __shared__ unsigned short sAl[128 * APAD];
    __shared__ unsigned short sBh[32 * BPAD];
    __shared__ unsigned short sBl[32 * BPAD];

    const int t    = threadIdx.x;
    const int lane = t & 31;
    const int warp = t >> 5;
    const int wr   = warp >> 2;   // 0..1  (64-row slab)
    const int wc   = warp & 3;    // 0..3  (32-col slab)

    // G2S mapping: A: 2 threads/row, 16 floats each; B: 8 threads/row, 16 floats each
    const int a_row = t >> 1, a_k = (t & 1) << 4;
    const int b_k   = t >> 3, b_n = (t & 7) << 4;

    const float* Ag = A + (size_t)(blockIdx.y * 128 + a_row) * K + a_k;
    const float* Wg = W + (size_t)b_k * N + blockIdx.x * 128 + b_n;

    float acc[4][4][4];
#pragma unroll
    for (int i = 0; i < 4; i++)
#pragma unroll
        for (int j = 0; j < 4; j++)
#pragma unroll
            for (int q = 0; q < 4; q++) acc[i][j][q] = 0.f;

    // ldmatrix per-lane offsets (element units)
    const int a_lm = (lane & 15) * APAD + (lane >> 4) * 8;
    const int b_lm = (lane & 15) * BPAD + (lane >> 4) * 8;

    for (int k0 = 0; k0 < K; k0 += 32) {
        // --- G2S: load fp32, split into (hi, lo) bf16, store to smem ---
#pragma unroll
        for (int u = 0; u < 4; u++) {
            float4 v = *(const float4*)(Ag + k0 + u * 4);
            uint32_t ph[2], pl[2];
            split4(v, ph, pl);
            *(uint2*)&sAh[a_row * APAD + a_k + u * 4] = make_uint2(ph[0], ph[1]);
            *(uint2*)&sAl[a_row * APAD + a_k + u * 4] = make_uint2(pl[0], pl[1]);
        }
#pragma unroll
        for (int u = 0; u < 4; u++) {
            float4 v = *(const float4*)(Wg + (size_t)k0 * N + u * 4);
            uint32_t ph[2], pl[2];
            split4(v, ph, pl);
            *(uint2*)&sBh[b_k * BPAD + b_n + u * 4] = make_uint2(ph[0], ph[1]);
            *(uint2*)&sBl[b_k * BPAD + b_n + u * 4] = make_uint2(pl[0], pl[1]);
        }
        __syncthreads();

        // --- MMA over 2 k16 steps ---
#pragma unroll
        for (int ks = 0; ks < 2; ks++) {
            uint32_t ah[4][4], al[4][4];
#pragma unroll
            for (int mt = 0; mt < 4; mt++) {
                const int base = (wr * 64 + mt * 16) * APAD + ks * 16;
                ldsm_x4(ah[mt], smem_u32(&sAh[base + a_lm]));
                ldsm_x4(al[mt], smem_u32(&sAl[base + a_lm]));
            }
#pragma unroll
            for (int np = 0; np < 2; np++) {
                uint32_t bh[4], bl[4];
                const int base = (ks * 16) * BPAD + wc * 32 + np * 16;
                ldsm_x4t(bh, smem_u32(&sBh[base + b_lm]));
                ldsm_x4t(bl, smem_u32(&sBl[base + b_lm]));
#pragma unroll
                for (int mt = 0; mt < 4; mt++) {
                    mma16816(acc[mt][np * 2 + 0], ah[mt], bh[0], bh[1]);
                    mma16816(acc[mt][np * 2 + 0], ah[mt], bl[0], bl[1]);
                    mma16816(acc[mt][np * 2 + 0], al[mt], bh[0], bh[1]);
                    mma16816(acc[mt][np * 2 + 1], ah[mt], bh[2], bh[3]);
                    mma16816(acc[mt][np * 2 + 1], ah[mt], bl[2], bl[3]);
                    mma16816(acc[mt][np * 2 + 1], al[mt], bh[2], bh[3]);
                }
            }
        }
        __syncthreads();
    }

    // --- epilogue: C layout c0:(g, 2t) c1:(g, 2t+1) c2:(g+8, 2t) c3:(g+8, 2t+1) ---
    const int g  = lane >> 2;
    const int tq = lane & 3;
    const int rowBase = blockIdx.y * 128 + wr * 64;
    const int colBase = blockIdx.x * 128 + wc * 32;

#pragma unroll
    for (int mt = 0; mt < 4; mt++) {
#pragma unroll
        for (int nt = 0; nt < 4; nt++) {
            const int row = rowBase + mt * 16 + g;
            const int col = colBase + nt * 8 + tq * 2;
            float b0 = 0.f, b1 = 0.f;
            if (EPI >= 1) { b0 = bias[col]; b1 = bias[col + 1]; }
            float v0 = acc[mt][nt][0] + b0;
            float v1 = acc[mt][nt][1] + b1;
            float v2 = acc[mt][nt][2] + b0;
            float v3 = acc[mt][nt][3] + b1;
            if (EPI == 2) {
                v0 = 0.5f * v0 * (1.0f + erff(v0 * 0.7071067811865475f));
                v1 = 0.5f * v1 * (1.0f + erff(v1 * 0.7071067811865475f));
                v2 = 0.5f * v2 * (1.0f + erff(v2 * 0.7071067811865475f));
                v3 = 0.5f * v3 * (1.0f + erff(v3 * 0.7071067811865475f));
            }
            float2 w0 = make_float2(v0, v1);
            float2 w1 = make_float2(v2, v3);
            *(float2*)&C[(size_t)row * N + col]       = w0;
            *(float2*)&C[(size_t)(row + 8) * N + col] = w1;
        }
    }
}

// ---------------------------------------------------------------------------
// Causal flash attention (fp32 SIMT, unchanged from R1).
// Grid: (S/64, H, B). Block: 256 threads = 16x16, 4x4 microtiles.
// ---------------------------------------------------------------------------
__global__ __launch_bounds__(256) void attn_kernel(
    const float* __restrict__ Q, const float* __restrict__ K,
    const float* __restrict__ V, float* __restrict__ O)
{
    __shared__ float sQt[64][64];
    __shared__ float sKt[64][64];
    __shared__ float sV[64][64];

    const int qb = blockIdx.x;
    const int h  = blockIdx.y;
    const int b  = blockIdx.z;
    const int t  = threadIdx.x;
    const int tx = t & 15;
    const int ty = t >> 4;
    const int q0 = qb << 6;

    const int lr = t >> 2;
    const int ld = (t & 3) << 4;

    {
        const float* qg = Q + (size_t)(b * SEQLEN + q0 + lr) * DMODEL + h * DHEAD + ld;
#pragma unroll
        for (int u = 0; u < 4; u++) {
            float4 v4 = *(const float4*)(qg + u * 4);
            sQt[ld + u * 4 + 0][lr] = v4.x * 0.125f;
            sQt[ld + u * 4 + 1][lr] = v4.y * 0.125f;
            sQt[ld + u * 4 + 2][lr] = v4.z * 0.125f;
            sQt[ld + u * 4 + 3][lr] = v4.w * 0.125f;
        }
    }

    float m[4], l[4], o[4][4];
#pragma unroll
    for (int i = 0; i < 4; i++) {
        m[i] = -1e30f;
        l[i] = 0.f;
#pragma unroll
        for (int j = 0; j < 4; j++) o[i][j] = 0.f;
    }

    for (int jb = 0; jb <= qb; jb++) {
        __syncthreads();
        const int j0 = jb << 6;
        {
            const float* kg = K + (size_t)(b * SEQLEN + j0 + lr) * DMODEL + h * DHEAD + ld;
            const float* vg = V + (size_t)(b * SEQLEN + j0 + lr) * DMODEL + h * DHEAD + ld;
#pragma unroll
            for (int u = 0; u < 4; u++) {
                float4 kv = *(const float4*)(kg + u * 4);
                sKt[ld + u * 4 + 0][lr] = kv.x;
                sKt[ld + u * 4 + 1][lr] = kv.y;
                sKt[ld + u * 4 + 2][lr] = kv.z;
                sKt[ld + u * 4 + 3][lr] = kv.w;
                *(float4*)&sV[lr][ld + u * 4] = *(const float4*)(vg + u * 4);
            }
        }
        __syncthreads();

        float s[4][4] = {};
#pragma unroll 8
        for (int d = 0; d < 64; d++) {
            float4 a4 = *(const float4*)&sQt[d][ty << 2];
            float4 b4 = *(const float4*)&sKt[d][tx << 2];
            float ar[4] = {a4.x, a4.y, a4.z, a4.w};
            float br[4] = {b4.x, b4.y, b4.z, b4.w};
#pragma unroll
            for (int i = 0; i < 4; i++)
#pragma unroll
                for (int j = 0; j < 4; j++)
                    s[i][j] = fmaf(ar[i], br[j], s[i][j]);
        }

        if (jb == qb) {
#pragma unroll
            for (int i = 0; i < 4; i++)
#pragma unroll
                for (int j = 0; j < 4; j++)
                    if ((tx << 2) + j > (ty << 2) + i) s[i][j] = -1e30f;
        }

        float newm[4], rsum[4], scale[4];
#pragma unroll
        for (int i = 0; i < 4; i++) {
            float rm = fmaxf(fmaxf(s[i][0], s[i][1]), fmaxf(s[i][2], s[i][3]));
#pragma unroll
            for (int off = 8; off; off >>= 1)
                rm = fmaxf(rm, __shfl_xor_sync(0xffffffffu, rm, off));
            newm[i] = fmaxf(m[i], rm);
            float rs = 0.f;
#pragma unroll
            for (int j = 0; j < 4; j++) {
                s[i][j] = __expf(s[i][j] - newm[i]);
                rs += s[i][j];
            }
#pragma unroll
            for (int off = 8; off; off >>= 1)
                rs += __shfl_xor_sync(0xffffffffu, rs, off);
            rsum[i]  = rs;
            scale[i] = __expf(m[i] - newm[i]);
            l[i] = l[i] * scale[i] + rsum[i];
            m[i] = newm[i];
#pragma unroll
            for (int j = 0; j < 4; j++) o[i][j] *= scale[i];
        }

        __syncthreads();

#pragma unroll
        for (int i = 0; i < 4; i++)
#pragma unroll
            for (int j = 0; j < 4; j++)
                sKt[(tx << 2) + j][(ty << 2) + i] = s[i][j];
        __syncthreads();

#pragma unroll 8
        for (int kk = 0; kk < 64; kk++) {
            float4 a4 = *(const float4*)&sKt[kk][ty << 2];
            float4 b4 = *(const float4*)&sV[kk][tx << 2];
            float ar[4] = {a4.x, a4.y, a4.z, a4.w};
            float br[4] = {b4.x, b4.y, b4.z, b4.w};
#pragma unroll
            for (int i = 0; i < 4; i++)
#pragma unroll
                for (int j = 0; j < 4; j++)
                    o[i][j] = fmaf(ar[i], br[j], o[i][j]);
        }
    }

#pragma unroll
    for (int i = 0; i < 4; i++) {
        float inv = 1.0f / l[i];
        float* og = O + (size_t)(b * SEQLEN + q0 + (ty << 2) + i) * DMODEL + h * DHEAD + (tx << 2);
        float4 v;
        v.x = o[i][0] * inv; v.y = o[i][1] * inv; v.z = o[i][2] * inv; v.w = o[i][3] * inv;
        *(float4*)og = v;
    }
}

// ---------------------------------------------------------------------------
// out[row] = xres[row] + LayerNorm(t[row]) * g + b
// ---------------------------------------------------------------------------
__global__ __launch_bounds__(256) void ln_res_kernel(
    const float* __restrict__ xres, const float* __restrict__ tin,
    const float* __restrict__ gam, const float* __restrict__ bet,
    float* __restrict__ out)
{
    const int row = blockIdx.x;
    const int tid = threadIdx.x;
    const float* tr = tin + (size_t)row * DMODEL;

    __shared__ float red[256];
    __shared__ float s_mu, s_rstd;

    float sum = 0.f, sq = 0.f;
    for (int c = tid; c < DMODEL; c += 256) {
        float v = tr[c];
        sum += v;
        sq  += v * v;
    }
    red[tid] = sum;
    __syncthreads();
    for (int s = 128; s > 0; s >>= 1) {
        if (tid < s) red[tid] += red[tid + s];
        __syncthreads();
    }
    if (tid == 0) s_mu = red[0] * (1.0f / DMODEL);
    __syncthreads();
    red[tid] = sq;
    __syncthreads();
    for (int s = 128; s > 0; s >>= 1) {
        if (tid < s) red[tid] += red[tid + s];
        __syncthreads();
    }
    if (tid == 0) {
        float mu  = s_mu;
        float var = red[0] * (1.0f / DMODEL) - mu * mu;
        s_rstd = rsqrtf(var + 1e-5f);
    }
    __syncthreads();

    const float mu = s_mu, rstd = s_rstd;
    for (int c = tid; c < DMODEL; c += 256) {
        out[(size_t)row * DMODEL + c] =
            xres[(size_t)row * DMODEL + c] + (tr[c] - mu) * rstd * gam[c] + bet[c];
    }
}

// ---------------------------------------------------------------------------
extern "C" void kernel_launch(void* const* d_in, const int* in_sizes, int n_in,
                              void* d_out, int out_size)
{
    const float* x    = (const float*)d_in[0];
    const float* wq   = (const float*)d_in[1];
    const float* bq   = (const float*)d_in[2];
    const float* wk   = (const float*)d_in[3];
    const float* bk   = (const float*)d_in[4];
    const float* wv   = (const float*)d_in[5];
    const float* bv   = (const float*)d_in[6];
    const float* wo   = (const float*)d_in[7];
    const float* ln1g = (const float*)d_in[8];
    const float* ln1b = (const float*)d_in[9];
    const float* w1   = (const float*)d_in[10];
    const float* b1   = (const float*)d_in[11];
    const float* w2   = (const float*)d_in[12];
    const float* ln2g = (const float*)d_in[13];
    const float* ln2b = (const float*)d_in[14];
    float* out = (float*)d_out;

    void *pQ, *pK, *pV, *pCtx, *pX1, *pH;
    cudaGetSymbolAddress(&pQ,   g_Q);
    cudaGetSymbolAddress(&pK,   g_K);
    cudaGetSymbolAddress(&pV,   g_V);
    cudaGetSymbolAddress(&pCtx, g_ctx);
    cudaGetSymbolAddress(&pX1,  g_x1);
    cudaGetSymbolAddress(&pH,   g_h);
    float* Q   = (float*)pQ;
    float* Kc  = (float*)pK;
    float* V   = (float*)pV;
    float* ctx = (float*)pCtx;
    float* x1  = (float*)pX1;
    float* h   = (float*)pH;

    const dim3 thr(256);

    // 1) QKV projections (tensor cores, bf16x3)
    gemm_bf16x3<1><<<dim3(8, 32), thr>>>(x, wq, bq, Q,  TOK, DMODEL, DMODEL);
    gemm_bf16x3<1><<<dim3(8, 32), thr>>>(x, wk, bk, Kc, TOK, DMODEL, DMODEL);
    gemm_bf16x3<1><<<dim3(8, 32), thr>>>(x, wv, bv, V,  TOK, DMODEL, DMODEL);

    // 2) Causal flash attention -> ctx
    attn_kernel<<<dim3(SEQLEN / 64, NHEADS, 2), thr>>>(Q, Kc, V, ctx);

    // 3) Output projection (no bias) -> h (temp [TOK, DMODEL])
    gemm_bf16x3<0><<<dim3(8, 32), thr>>>(ctx, wo, nullptr, h, TOK, DMODEL, DMODEL);

    // 4) x1 = x + LN1(h)
    ln_res_kernel<<<TOK, thr>>>(x, h, ln1g, ln1b, x1);

    // 5) h = gelu(x1 @ w1 + b1)
    gemm_bf16x3<2><<<dim3(32, 32), thr>>>(x1, w1, b1, h, TOK, DMODEL, DHID);

    // 6) ctx = h @ w2
    gemm_bf16x3<0><<<dim3(8, 32), thr>>>(h, w2, nullptr, ctx, TOK, DHID, DMODEL);

    // 7) out = x1 + LN2(ctx)
    ln_res_kernel<<<TOK, thr>>>(x1, ctx, ln2g, ln2b, out);
}

// round 3
// speedup vs baseline: 1.9010x; 1.2452x over previous
#include <cuda_runtime.h>
#include <cuda_bf16.h>
#include <math.h>
#include <stdint.h>

// Problem constants
#define TOK     4096      // B*S tokens
#define DMODEL  1024
#define DHID    4096
#define NHEADS  16
#define DHEAD   64
#define SEQLEN  2048

// Scratch (allocation-free: __device__ globals)
__device__ float g_Q[TOK * DMODEL];
__device__ float g_K[TOK * DMODEL];
__device__ float g_V[TOK * DMODEL];
__device__ float g_ctx[TOK * DMODEL];
__device__ float g_x1[TOK * DMODEL];
__device__ float g_h[TOK * DHID];

// ---------------------------------------------------------------------------
// Shared MMA helpers
// ---------------------------------------------------------------------------
__device__ __forceinline__ uint32_t smem_u32(const void* p) {
    return (uint32_t)__cvta_generic_to_shared(p);
}
__device__ __forceinline__ void ldsm_x4(uint32_t* r, uint32_t a) {
    asm volatile("ldmatrix.sync.aligned.m8n8.x4.shared.b16 {%0,%1,%2,%3},[%4];\n"
                 : "=r"(r[0]), "=r"(r[1]), "=r"(r[2]), "=r"(r[3]) : "r"(a));
}
__device__ __forceinline__ void ldsm_x4t(uint32_t* r, uint32_t a) {
    asm volatile("ldmatrix.sync.aligned.m8n8.x4.trans.shared.b16 {%0,%1,%2,%3},[%4];\n"
                 : "=r"(r[0]), "=r"(r[1]), "=r"(r[2]), "=r"(r[3]) : "r"(a));
}
__device__ __forceinline__ void mma16816(float* d, const uint32_t* a, uint32_t b0, uint32_t b1) {
    asm volatile("mma.sync.aligned.m16n8k16.row.col.f32.bf16.bf16.f32 "
                 "{%0,%1,%2,%3},{%4,%5,%6,%7},{%8,%9},{%0,%1,%2,%3};\n"
                 : "+f"(d[0]), "+f"(d[1]), "+f"(d[2]), "+f"(d[3])
                 : "r"(a[0]), "r"(a[1]), "r"(a[2]), "r"(a[3]), "r"(b0), "r"(b1));
}

__device__ __forceinline__ void split4(float4 v, uint32_t* ph, uint32_t* pl) {
    float f[4] = {v.x, v.y, v.z, v.w};
    unsigned short h[4], l[4];
#pragma unroll
    for (int i = 0; i < 4; i++) {
        __nv_bfloat16 bh = __float2bfloat16(f[i]);
        float r = f[i] - __bfloat162float(bh);
        __nv_bfloat16 bl = __float2bfloat16(r);
        h[i] = __bfloat16_as_ushort(bh);
        l[i] = __bfloat16_as_ushort(bl);
    }
    ph[0] = (uint32_t)h[0] | ((uint32_t)h[1] << 16);
    ph[1] = (uint32_t)h[2] | ((uint32_t)h[3] << 16);
    pl[0] = (uint32_t)l[0] | ((uint32_t)l[1] << 16);
    pl[1] = (uint32_t)l[2] | ((uint32_t)l[3] << 16);
}

__device__ __forceinline__ void split2(float x, float y, uint32_t& hi, uint32_t& lo) {
    __nv_bfloat16 hx = __float2bfloat16(x), hy = __float2bfloat16(y);
    float rx = x - __bfloat162float(hx), ry = y - __bfloat162float(hy);
    __nv_bfloat16 lx = __float2bfloat16(rx), ly = __float2bfloat16(ry);
    hi = (uint32_t)__bfloat16_as_ushort(hx) | ((uint32_t)__bfloat16_as_ushort(hy) << 16);
    lo = (uint32_t)__bfloat16_as_ushort(lx) | ((uint32_t)__bfloat16_as_ushort(ly) << 16);
}

// ---------------------------------------------------------------------------
// bf16x3 split-precision tensor-core GEMM (unchanged from R2).
// CTA tile 128x128, BK=32, 256 threads = 8 warps in 2x4, warp tile 64x32.
// ---------------------------------------------------------------------------
#define APAD 40
#define BPAD 136

template <int EPI>
__global__ __launch_bounds__(256) void gemm_bf16x3(
    const float* __restrict__ A, const float* __restrict__ W,
    const float* __restrict__ bias, float* __restrict__ C,
    int M, int K, int N)
{
    __shared__ unsigned short sAh[128 * APAD];
    __shared__ unsigned short sAl[128 * APAD];
    __shared__ unsigned short sBh[32 * BPAD];
    __shared__ unsigned short sBl[32 * BPAD];

    const int t    = threadIdx.x;
    const int lane = t & 31;
    const int warp = t >> 5;
    const int wr   = warp >> 2;
    const int wc   = warp & 3;

    const int a_row = t >> 1, a_k = (t & 1) << 4;
    const int b_k   = t >> 3, b_n = (t & 7) << 4;

    const float* Ag = A + (size_t)(blockIdx.y * 128 + a_row) * K + a_k;
    const float* Wg = W + (size_t)b_k * N + blockIdx.x * 128 + b_n;

    float acc[4][4][4];
#pragma unroll
    for (int i = 0; i < 4; i++)
#pragma unroll
        for (int j = 0; j < 4; j++)
#pragma unroll
            for (int q = 0; q < 4; q++) acc[i][j][q] = 0.f;

    const int a_lm = (lane & 15) * APAD + (lane >> 4) * 8;
    const int b_lm = (lane & 15) * BPAD + (lane >> 4) * 8;

    for (int k0 = 0; k0 < K; k0 += 32) {
#pragma unroll
        for (int u = 0; u < 4; u++) {
            float4 v = *(const float4*)(Ag + k0 + u * 4);
            uint32_t ph[2], pl[2];
            split4(v, ph, pl);
            *(uint2*)&sAh[a_row * APAD + a_k + u * 4] = make_uint2(ph[0], ph[1]);
            *(uint2*)&sAl[a_row * APAD + a_k + u * 4] = make_uint2(pl[0], pl[1]);
        }
#pragma unroll
        for (int u = 0; u < 4; u++) {
            float4 v = *(const float4*)(Wg + (size_t)k0 * N + u * 4);
            uint32_t ph[2], pl[2];
            split4(v, ph, pl);
            *(uint2*)&sBh[b_k * BPAD + b_n + u * 4] = make_uint2(ph[0], ph[1]);
            *(uint2*)&sBl[b_k * BPAD + b_n + u * 4] = make_uint2(pl[0], pl[1]);
        }
        __syncthreads();

#pragma unroll
        for (int ks = 0; ks < 2; ks++) {
            uint32_t ah[4][4], al[4][4];
#pragma unroll
            for (int mt = 0; mt < 4; mt++) {
                const int base = (wr * 64 + mt * 16) * APAD + ks * 16;
                ldsm_x4(ah[mt], smem_u32(&sAh[base + a_lm]));
                ldsm_x4(al[mt], smem_u32(&sAl[base + a_lm]));
            }
#pragma unroll
            for (int np = 0; np < 2; np++) {
                uint32_t bh[4], bl[4];
                const int base = (ks * 16) * BPAD + wc * 32 + np * 16;
                ldsm_x4t(bh, smem_u32(&sBh[base + b_lm]));
                ldsm_x4t(bl, smem_u32(&sBl[base + b_lm]));
#pragma unroll
                for (int mt = 0; mt < 4; mt++) {
                    mma16816(acc[mt][np * 2 + 0], ah[mt], bh[0], bh[1]);
                    mma16816(acc[mt][np * 2 + 0], ah[mt], bl[0], bl[1]);
                    mma16816(acc[mt][np * 2 + 0], al[mt], bh[0], bh[1]);
                    mma16816(acc[mt][np * 2 + 1], ah[mt], bh[2], bh[3]);
                    mma16816(acc[mt][np * 2 + 1], ah[mt], bl[2], bl[3]);
                    mma16816(acc[mt][np * 2 + 1], al[mt], bh[2], bh[3]);
                }
            }
        }
        __syncthreads();
    }

    const int g  = lane >> 2;
    const int tq = lane & 3;
    const int rowBase = blockIdx.y * 128 + wr * 64;
    const int colBase = blockIdx.x * 128 + wc * 32;

#pragma unroll
    for (int mt = 0; mt < 4; mt++) {
#pragma unroll
        for (int nt = 0; nt < 4; nt++) {
            const int row = rowBase + mt * 16 + g;
            const int col = colBase + nt * 8 + tq * 2;
            float b0 = 0.f, b1 = 0.f;
            if (EPI >= 1) { b0 = bias[col]; b1 = bias[col + 1]; }
            float v0 = acc[mt][nt][0] + b0;
            float v1 = acc[mt][nt][1] + b1;
            float v2 = acc[mt][nt][2] + b0;
            float v3 = acc[mt][nt][3] + b1;
            if (EPI == 2) {
                v0 = 0.5f * v0 * (1.0f + erff(v0 * 0.7071067811865475f));
                v1 = 0.5f * v1 * (1.0f + erff(v1 * 0.7071067811865475f));
                v2 = 0.5f * v2 * (1.0f + erff(v2 * 0.7071067811865475f));
                v3 = 0.5f * v3 * (1.0f + erff(v3 * 0.7071067811865475f));
            }
            *(float2*)&C[(size_t)row * N + col]       = make_float2(v0, v1);
            *(float2*)&C[(size_t)(row + 8) * N + col] = make_float2(v2, v3);
        }
    }
}

// ---------------------------------------------------------------------------
// Tensor-core causal flash attention, bf16x3 for both QK^T and P·V.
// Grid: (S/64, H, B). Block: 128 threads = 4 warps; warp owns 16 query rows.
// Q fragments preloaded into registers (loop-invariant); smem holds K/V hi+lo.
// ---------------------------------------------------------------------------
#define KPAD 72   // 64 + 8 halves; ldmatrix conflict-free (144B row stride)

__global__ __launch_bounds__(128) void attn_tc_kernel(
    const float* __restrict__ Q, const float* __restrict__ K,
    const float* __restrict__ V, float* __restrict__ O)
{
    __shared__ unsigned short sKh[64 * KPAD];
    __shared__ unsigned short sKl[64 * KPAD];
    __shared__ unsigned short sVh[64 * KPAD];
    __shared__ unsigned short sVl[64 * KPAD];

    const int qb = blockIdx.x;
    const int h  = blockIdx.y;
    const int b  = blockIdx.z;
    const int t  = threadIdx.x;
    const int lane = t & 31;
    const int warp = t >> 5;          // warp wr: query rows [wr*16, wr*16+16)
    const int q0 = qb << 6;

    const int g  = lane >> 2;         // 0..7
    const int tq = lane & 3;          // 0..3

    // loader mapping: 2 threads per row, 32 floats each
    const int lr = t >> 1;
    const int lc = (t & 1) << 5;

    const int lm = (lane & 15) * KPAD + (lane >> 4) * 8;   // ldmatrix lane offset

    // ---- Stage Q (scaled by 1/8) into sKh/sKl, then preload fragments ----
    {
        const float* qg = Q + (size_t)(b * SEQLEN + q0 + lr) * DMODEL + h * DHEAD + lc;
#pragma unroll
        for (int u = 0; u < 8; u++) {
            float4 v = *(const float4*)(qg + u * 4);
            v.x *= 0.125f; v.y *= 0.125f; v.z *= 0.125f; v.w *= 0.125f;
            uint32_t ph[2], pl[2];
            split4(v, ph, pl);
            *(uint2*)&sKh[lr * KPAD + lc + u * 4] = make_uint2(ph[0], ph[1]);
            *(uint2*)&sKl[lr * KPAD + lc + u * 4] = make_uint2(pl[0], pl[1]);
        }
    }
    __syncthreads();

    uint32_t qh[4][4], ql[4][4];      // [kc over d][frag]
#pragma unroll
    for (int kc = 0; kc < 4; kc++) {
        const int base = (warp * 16) * KPAD + kc * 16 + lm;
        ldsm_x4(qh[kc], smem_u32(&sKh[base]));
        ldsm_x4(ql[kc], smem_u32(&sKl[base]));
    }
    __syncthreads();

    float m0 = -1e30f, m1 = -1e30f, l0 = 0.f, l1 = 0.f;
    float o[8][4];
#pragma unroll
    for (int j = 0; j < 8; j++)
#pragma unroll
        for (int q = 0; q < 4; q++) o[j][q] = 0.f;

    for (int jb = 0; jb <= qb; jb++) {
        const int j0 = jb << 6;
        // ---- Load K/V tile, split to bf16 hi/lo ----
        {
            const float* kg = K + (size_t)(b * SEQLEN + j0 + lr) * DMODEL + h * DHEAD + lc;
            const float* vg = V + (size_t)(b * SEQLEN + j0 + lr) * DMODEL + h * DHEAD + lc;
#pragma unroll
            for (int u = 0; u < 8; u++) {
                uint32_t ph[2], pl[2];
                split4(*(const float4*)(kg + u * 4), ph, pl);
                *(uint2*)&sKh[lr * KPAD + lc + u * 4] = make_uint2(ph[0], ph[1]);
                *(uint2*)&sKl[lr * KPAD + lc + u * 4] = make_uint2(pl[0], pl[1]);
                split4(*(const float4*)(vg + u * 4), ph, pl);
                *(uint2*)&sVh[lr * KPAD + lc + u * 4] = make_uint2(ph[0], ph[1]);
                *(uint2*)&sVl[lr * KPAD + lc + u * 4] = make_uint2(pl[0], pl[1]);
            }
        }
        __syncthreads();

        // ---- S = Q K^T : warp computes 16 x 64 ----
        float s[8][4];
#pragma unroll
        for (int j = 0; j < 8; j++)
#pragma unroll
            for (int q = 0; q < 4; q++) s[j][q] = 0.f;

#pragma unroll
        for (int kc = 0; kc < 4; kc++) {          // d chunks of 16
#pragma unroll
            for (int kt = 0; kt < 4; kt++) {      // key groups of 16
                uint32_t kbh[4], kbl[4];
                const int base = (kt * 16) * KPAD + kc * 16 + lm;
                ldsm_x4(kbh, smem_u32(&sKh[base]));
                ldsm_x4(kbl, smem_u32(&sKl[base]));
                // n8 tile j = kt*2   : b = {r0, r2};  j = kt*2+1 : b = {r1, r3}
                mma16816(s[kt * 2 + 0], qh[kc], kbh[0], kbh[2]);
                mma16816(s[kt * 2 + 0], qh[kc], kbl[0], kbl[2]);
                mma16816(s[kt * 2 + 0], ql[kc], kbh[0], kbh[2]);
                mma16816(s[kt * 2 + 1], qh[kc], kbh[1], kbh[3]);
                mma16816(s[kt * 2 + 1], qh[kc], kbl[1], kbl[3]);
                mma16816(s[kt * 2 + 1], ql[kc], kbh[1], kbh[3]);
            }
        }

        // ---- Causal mask on the diagonal block ----
        if (jb == qb) {
            const int r0 = warp * 16 + g;
            const int r1 = r0 + 8;
#pragma unroll
            for (int j = 0; j < 8; j++) {
                const int c0 = j * 8 + tq * 2;
                if (c0 > r0)     s[j][0] = -1e30f;
                if (c0 + 1 > r0) s[j][1] = -1e30f;
                if (c0 > r1)     s[j][2] = -1e30f;
                if (c0 + 1 > r1) s[j][3] = -1e30f;
            }
        }

        // ---- Online softmax (rows g and g+8 of the warp tile) ----
        float rm0 = -1e30f, rm1 = -1e30f;
#pragma unroll
        for (int j = 0; j < 8; j++) {
            rm0 = fmaxf(rm0, fmaxf(s[j][0], s[j][1]));
            rm1 = fmaxf(rm1, fmaxf(s[j][2], s[j][3]));
        }
        rm0 = fmaxf(rm0, __shfl_xor_sync(0xffffffffu, rm0, 1));
        rm0 = fmaxf(rm0, __shfl_xor_sync(0xffffffffu, rm0, 2));
        rm1 = fmaxf(rm1, __shfl_xor_sync(0xffffffffu, rm1, 1));
        rm1 = fmaxf(rm1, __shfl_xor_sync(0xffffffffu, rm1, 2));
        const float nm0 = fmaxf(m0, rm0);
        const float nm1 = fmaxf(m1, rm1);

        float rs0 = 0.f, rs1 = 0.f;
#pragma unroll
        for (int j = 0; j < 8; j++) {
            s[j][0] = __expf(s[j][0] - nm0);
            s[j][1] = __expf(s[j][1] - nm0);
            s[j][2] = __expf(s[j][2] - nm1);
            s[j][3] = __expf(s[j][3] - nm1);
            rs0 += s[j][0] + s[j][1];
            rs1 += s[j][2] + s[j][3];
        }
        rs0 += __shfl_xor_sync(0xffffffffu, rs0, 1);
        rs0 += __shfl_xor_sync(0xffffffffu, rs0, 2);
        rs1 += __shfl_xor_sync(0xffffffffu, rs1, 1);
        rs1 += __shfl_xor_sync(0xffffffffu, rs1, 2);

        const float sc0 = __expf(m0 - nm0);
        const float sc1 = __expf(m1 - nm1);
        l0 = l0 * sc0 + rs0;  m0 = nm0;
        l1 = l1 * sc1 + rs1;  m1 = nm1;
#pragma unroll
        for (int j = 0; j < 8; j++) {
            o[j][0] *= sc0; o[j][1] *= sc0;
            o[j][2] *= sc1; o[j][3] *= sc1;
        }

        // ---- O += P V  (P fragments packed from S accumulators) ----
#pragma unroll
        for (int kc = 0; kc < 4; kc++) {          // key chunks of 16
            uint32_t pah[4], pal[4];
            split2(s[2 * kc + 0][0], s[2 * kc + 0][1], pah[0], pal[0]);
            split2(s[2 * kc + 0][2], s[2 * kc + 0][3], pah[1], pal[1]);
            split2(s[2 * kc + 1][0], s[2 * kc + 1][1], pah[2], pal[2]);
            split2(s[2 * kc + 1][2], s[2 * kc + 1][3], pah[3], pal[3]);
#pragma unroll
            for (int dt = 0; dt < 4; dt++) {      // d groups of 16
                uint32_t vbh[4], vbl[4];
                const int base = (kc * 16) * KPAD + dt * 16 + lm;
                ldsm_x4t(vbh, smem_u32(&sVh[base]));
                ldsm_x4t(vbl, smem_u32(&sVl[base]));
                mma16816(o[dt * 2 + 0], pah, vbh[0], vbh[1]);
                mma16816(o[dt * 2 + 0], pah, vbl[0], vbl[1]);
                mma16816(o[dt * 2 + 0], pal, vbh[0], vbh[1]);
                mma16816(o[dt * 2 + 1], pah, vbh[2], vbh[3]);
                mma16816(o[dt * 2 + 1], pah, vbl[2], vbl[3]);
                mma16816(o[dt * 2 + 1], pal, vbh[2], vbh[3]);
            }
        }
        __syncthreads();   // done reading K/V before next tile overwrites
    }

    // ---- Write context ----
    const float inv0 = 1.0f / l0;
    const float inv1 = 1.0f / l1;
    const int row0 = q0 + warp * 16 + g;
#pragma unroll
    for (int j = 0; j < 8; j++) {
        const int col = h * DHEAD + j * 8 + tq * 2;
        *(float2*)&O[(size_t)(b * SEQLEN + row0) * DMODEL + col] =
            make_float2(o[j][0] * inv0, o[j][1] * inv0);
        *(float2*)&O[(size_t)(b * SEQLEN + row0 + 8) * DMODEL + col] =
            make_float2(o[j][2] * inv1, o[j][3] * inv1);
    }
}

// ---------------------------------------------------------------------------
// out[row] = xres[row] + LayerNorm(t[row]) * g + b
// ---------------------------------------------------------------------------
__global__ __launch_bounds__(256) void ln_res_kernel(
    const float* __restrict__ xres, const float* __restrict__ tin,
    const float* __restrict__ gam, const float* __restrict__ bet,
    float* __restrict__ out)
{
    const int row = blockIdx.x;
    const int tid = threadIdx.x;
    const float* tr = tin + (size_t)row * DMODEL;

    __shared__ float red[256];
    __shared__ float s_mu, s_rstd;

    float sum = 0.f, sq = 0.f;
    for (int c = tid; c < DMODEL; c += 256) {
        float v = tr[c];
        sum += v;
        sq  += v * v;
    }
    red[tid] = sum;
    __syncthreads();
    for (int s = 128; s > 0; s >>= 1) {
        if (tid < s) red[tid] += red[tid + s];
        __syncthreads();
    }
    if (tid == 0) s_mu = red[0] * (1.0f / DMODEL);
    __syncthreads();
    red[tid] = sq;
    __syncthreads();
    for (int s = 128; s > 0; s >>= 1) {
        if (tid < s) red[tid] += red[tid + s];
        __syncthreads();
    }
    if (tid == 0) {
        float mu  = s_mu;
        float var = red[0] * (1.0f / DMODEL) - mu * mu;
        s_rstd = rsqrtf(var + 1e-5f);
    }
    __syncthreads();

    const float mu = s_mu, rstd = s_rstd;
    for (int c = tid; c < DMODEL; c += 256) {
        out[(size_t)row * DMODEL + c] =
            xres[(size_t)row * DMODEL + c] + (tr[c] - mu) * rstd * gam[c] + bet[c];
    }
}

// ---------------------------------------------------------------------------
extern "C" void kernel_launch(void* const* d_in, const int* in_sizes, int n_in,
                              void* d_out, int out_size)
{
    const float* x    = (const float*)d_in[0];
    const float* wq   = (const float*)d_in[1];
    const float* bq   = (const float*)d_in[2];
    const float* wk   = (const float*)d_in[3];
    const float* bk   = (const float*)d_in[4];
    const float* wv   = (const float*)d_in[5];
    const float* bv   = (const float*)d_in[6];
    const float* wo   = (const float*)d_in[7];
    const float* ln1g = (const float*)d_in[8];
    const float* ln1b = (const float*)d_in[9];
    const float* w1   = (const float*)d_in[10];
    const float* b1   = (const float*)d_in[11];
    const float* w2   = (const float*)d_in[12];
    const float* ln2g = (const float*)d_in[13];
    const float* ln2b = (const float*)d_in[14];
    float* out = (float*)d_out;

    void *pQ, *pK, *pV, *pCtx, *pX1, *pH;
    cudaGetSymbolAddress(&pQ,   g_Q);
    cudaGetSymbolAddress(&pK,   g_K);
    cudaGetSymbolAddress(&pV,   g_V);
    cudaGetSymbolAddress(&pCtx, g_ctx);
    cudaGetSymbolAddress(&pX1,  g_x1);
    cudaGetSymbolAddress(&pH,   g_h);
    float* Q   = (float*)pQ;
    float* Kc  = (float*)pK;
    float* V   = (float*)pV;
    float* ctx = (float*)pCtx;
    float* x1  = (float*)pX1;
    float* h   = (float*)pH;

    // 1) QKV projections (tensor cores, bf16x3)
    gemm_bf16x3<1><<<dim3(8, 32), 256>>>(x, wq, bq, Q,  TOK, DMODEL, DMODEL);
    gemm_bf16x3<1><<<dim3(8, 32), 256>>>(x, wk, bk, Kc, TOK, DMODEL, DMODEL);
    gemm_bf16x3<1><<<dim3(8, 32), 256>>>(x, wv, bv, V,  TOK, DMODEL, DMODEL);

    // 2) Tensor-core causal flash attention -> ctx
    attn_tc_kernel<<<dim3(SEQLEN / 64, NHEADS, 2), 128>>>(Q, Kc, V, ctx);

    // 3) Output projection (no bias) -> h (temp [TOK, DMODEL])
    gemm_bf16x3<0><<<dim3(8, 32), 256>>>(ctx, wo, nullptr, h, TOK, DMODEL, DMODEL);

    // 4) x1 = x + LN1(h)
    ln_res_kernel<<<TOK, 256>>>(x, h, ln1g, ln1b, x1);

    // 5) h = gelu(x1 @ w1 + b1)
    gemm_bf16x3<2><<<dim3(32, 32), 256>>>(x1, w1, b1, h, TOK, DMODEL, DHID);

    // 6) ctx = h @ w2
    gemm_bf16x3<0><<<dim3(8, 32), 256>>>(h, w2, nullptr, ctx, TOK, DHID, DMODEL);

    // 7) out = x1 + LN2(ctx)
    ln_res_kernel<<<TOK, 256>>>(x1, ctx, ln2g, ln2b, out);
}

// round 4
// speedup vs baseline: 2.9924x; 1.5741x over previous
#include <cuda_runtime.h>
#include <cuda_bf16.h>
#include <math.h>
#include <stdint.h>

// Problem constants
#define TOK     4096
#define DMODEL  1024
#define DHID    4096
#define NHEADS  16
#define DHEAD   64
#define SEQLEN  2048

typedef unsigned short ushort_t;

// ---------------- Scratch (allocation-free __device__ globals) -------------
// Split activations
__device__ ushort_t g_xh[TOK * DMODEL],  g_xl[TOK * DMODEL];
__device__ ushort_t g_Qh[TOK * DMODEL],  g_Ql[TOK * DMODEL];
__device__ ushort_t g_Kh[TOK * DMODEL],  g_Kl[TOK * DMODEL];
__device__ ushort_t g_Vh[TOK * DMODEL],  g_Vl[TOK * DMODEL];
__device__ ushort_t g_ctxh[TOK * DMODEL], g_ctxl[TOK * DMODEL];
__device__ ushort_t g_x1h[TOK * DMODEL], g_x1l[TOK * DMODEL];
__device__ ushort_t g_hh[TOK * DHID],    g_hl[TOK * DHID];
// fp32 buffers
__device__ float g_x1[TOK * DMODEL];
__device__ float g_tmp[TOK * DMODEL];
// Split weights
__device__ ushort_t g_wqh[DMODEL * DMODEL], g_wql[DMODEL * DMODEL];
__device__ ushort_t g_wkh[DMODEL * DMODEL], g_wkl[DMODEL * DMODEL];
__device__ ushort_t g_wvh[DMODEL * DMODEL], g_wvl[DMODEL * DMODEL];
__device__ ushort_t g_woh[DMODEL * DMODEL], g_wol[DMODEL * DMODEL];
__device__ ushort_t g_w1h[DMODEL * DHID],   g_w1l[DMODEL * DHID];
__device__ ushort_t g_w2h[DHID * DMODEL],   g_w2l[DHID * DMODEL];

// ---------------------------------------------------------------------------
// Helpers
// ---------------------------------------------------------------------------
__device__ __forceinline__ uint32_t smem_u32(const void* p) {
    return (uint32_t)__cvta_generic_to_shared(p);
}
__device__ __forceinline__ void ldsm_x4(uint32_t* r, uint32_t a) {
    asm volatile("ldmatrix.sync.aligned.m8n8.x4.shared.b16 {%0,%1,%2,%3},[%4];\n"
                 : "=r"(r[0]), "=r"(r[1]), "=r"(r[2]), "=r"(r[3]) : "r"(a));
}
__device__ __forceinline__ void ldsm_x4t(uint32_t* r, uint32_t a) {
    asm volatile("ldmatrix.sync.aligned.m8n8.x4.trans.shared.b16 {%0,%1,%2,%3},[%4];\n"
                 : "=r"(r[0]), "=r"(r[1]), "=r"(r[2]), "=r"(r[3]) : "r"(a));
}
__device__ __forceinline__ void mma16816(float* d, const uint32_t* a, uint32_t b0, uint32_t b1) {
    asm volatile("mma.sync.aligned.m16n8k16.row.col.f32.bf16.bf16.f32 "
                 "{%0,%1,%2,%3},{%4,%5,%6,%7},{%8,%9},{%0,%1,%2,%3};\n"
                 : "+f"(d[0]), "+f"(d[1]), "+f"(d[2]), "+f"(d[3])
                 : "r"(a[0]), "r"(a[1]), "r"(a[2]), "r"(a[3]), "r"(b0), "r"(b1));
}
__device__ __forceinline__ void cp16(uint32_t dst, const void* src) {
    asm volatile("cp.async.ca.shared.global [%0], [%1], 16;\n" :: "r"(dst), "l"(src));
}
__device__ __forceinline__ void cp_commit() {
    asm volatile("cp.async.commit_group;\n");
}
template <int N>
__device__ __forceinline__ void cp_wait() {
    asm volatile("cp.async.wait_group %0;\n" :: "n"(N));
}

__device__ __forceinline__ void split2(float x, float y, uint32_t& hi, uint32_t& lo) {
    __nv_bfloat16 hx = __float2bfloat16(x), hy = __float2bfloat16(y);
    float rx = x - __bfloat162float(hx), ry = y - __bfloat162float(hy);
    __nv_bfloat16 lx = __float2bfloat16(rx), ly = __float2bfloat16(ry);
    hi = (uint32_t)__bfloat16_as_ushort(hx) | ((uint32_t)__bfloat16_as_ushort(hy) << 16);
    lo = (uint32_t)__bfloat16_as_ushort(lx) | ((uint32_t)__bfloat16_as_ushort(ly) << 16);
}

// ---------------------------------------------------------------------------
// Elementwise fp32 -> (hi, lo) bf16 split. 256 threads, float4 per thread.
// ---------------------------------------------------------------------------
__global__ __launch_bounds__(256) void split_kernel(
    const float4* __restrict__ in, uint2* __restrict__ hi, uint2* __restrict__ lo)
{
    const int idx = blockIdx.x * 256 + threadIdx.x;
    float4 v = in[idx];
    uint32_t h0, l0, h1, l1;
    split2(v.x, v.y, h0, l0);
    split2(v.z, v.w, h1, l1);
    hi[idx] = make_uint2(h0, h1);
    lo[idx] = make_uint2(l0, l1);
}

// ---------------------------------------------------------------------------
// Pipelined bf16x3 GEMM. Inputs pre-split (Ah/Al [M,K], Wh/Wl [K,N]).
// CTA 128x128, BK=32, 256 thr = 8 warps (2x4), 2-stage cp.async pipeline.
// EPI: 0 none | 1 +bias | 2 +bias,gelu | 3 (+bias)*0.125
// OUT: 0 fp32 Cf | 1 split Ch/Cl
// ---------------------------------------------------------------------------
#define APAD 40
#define BPAD 136
#define OFF_AH 0
#define OFF_AL (128 * APAD * 2)
#define OFF_BH (OFF_AL + 128 * APAD * 2)
#define OFF_BL (OFF_BH + 32 * BPAD * 2)
#define STAGE_BYTES (OFF_BL + 32 * BPAD * 2)   // 37888
#define GEMM_SMEM (2 * STAGE_BYTES)            // 75776

template <int EPI, int OUT>
__global__ __launch_bounds__(256) void gemm_pipe(
    const ushort_t* __restrict__ Ah, const ushort_t* __restrict__ Al,
    const ushort_t* __restrict__ Wh, const ushort_t* __restrict__ Wl,
    const float* __restrict__ bias,
    float* __restrict__ Cf, ushort_t* __restrict__ Ch, ushort_t* __restrict__ Cl,
    int M, int K, int N)
{
    extern __shared__ char smem[];
    const uint32_t sbase = smem_u32(smem);

    const int t    = threadIdx.x;
    const int lane = t & 31;
    const int warp = t >> 5;
    const int wr   = warp >> 2;
    const int wc   = warp & 3;

    const int rowBase = blockIdx.y * 128;
    const int colBase = blockIdx.x * 128;

    // cp.async mapping
    const int ar = t >> 2;            // 0..63 (rows ar, ar+64)
    const int ac = (t & 3) << 3;      // bf16 col {0,8,16,24}
    const int br = t >> 3;            // 0..31
    const int bc = (t & 7) << 3;      // bf16 col {0..56}, +64

    const ushort_t* Agh = Ah + (size_t)(rowBase + ar) * K + ac;
    const ushort_t* Agl = Al + (size_t)(rowBase + ar) * K + ac;
    const ushort_t* Wgh = Wh + (size_t)br * N + colBase + bc;
    const ushort_t* Wgl = Wl + (size_t)br * N + colBase + bc;

    const uint32_t dA0 = (uint32_t)(ar * APAD + ac) * 2;
    const uint32_t dA1 = (uint32_t)((ar + 64) * APAD + ac) * 2;
    const uint32_t dB0 = (uint32_t)(br * BPAD + bc) * 2;
    const uint32_t dB1 = (uint32_t)(br * BPAD + bc + 64) * 2;

    const int ntiles = K >> 5;

#define LOAD_STAGE(s, k0)                                                        \
    do {                                                                         \
        const uint32_t sb = sbase + (s) * STAGE_BYTES;                           \
        cp16(sb + OFF_AH + dA0, Agh + (k0));                                     \
        cp16(sb + OFF_AH + dA1, Agh + (size_t)64 * K + (k0));                    \
        cp16(sb + OFF_AL + dA0, Agl + (k0));                                     \
        cp16(sb + OFF_AL + dA1, Agl + (size_t)64 * K + (k0));                    \
        cp16(sb + OFF_BH + dB0, Wgh + (size_t)(k0) * N);                         \
        cp16(sb + OFF_BH + dB1, Wgh + (size_t)(k0) * N + 64);                    \
        cp16(sb + OFF_BL + dB0, Wgl + (size_t)(k0) * N);                         \
        cp16(sb + OFF_BL + dB1, Wgl + (size_t)(k0) * N + 64);                    \
    } while (0)

    float acc[4][4][4];
#pragma unroll
    for (int i = 0; i < 4; i++)
#pragma unroll
        for (int j = 0; j < 4; j++)
#pragma unroll
            for (int q = 0; q < 4; q++) acc[i][j][q] = 0.f;

    const int a_lm = (lane & 15) * APAD + (lane >> 4) * 8;
    const int b_lm = (lane & 15) * BPAD + (lane >> 4) * 8;

    LOAD_STAGE(0, 0);
    cp_commit();

    for (int kt = 0; kt < ntiles; kt++) {
        if (kt + 1 < ntiles) LOAD_STAGE((kt + 1) & 1, (kt + 1) << 5);
        cp_commit();
        cp_wait<1>();
        __syncthreads();

        const uint32_t sb = sbase + (kt & 1) * STAGE_BYTES;
#pragma unroll
        for (int ks = 0; ks < 2; ks++) {
            uint32_t ah[4][4], al[4][4];
#pragma unroll
            for (int mt = 0; mt < 4; mt++) {
                const uint32_t base = sb + 2 * ((wr * 64 + mt * 16) * APAD + ks * 16 + a_lm);
                ldsm_x4(ah[mt], base + OFF_AH);
                ldsm_x4(al[mt], base + OFF_AL);
            }
#pragma unroll
            for (int np = 0; np < 2; np++) {
                uint32_t bh[4], bl[4];
                const uint32_t base = sb + 2 * ((ks * 16) * BPAD + wc * 32 + np * 16 + b_lm);
                ldsm_x4t(bh, base + OFF_BH);
                ldsm_x4t(bl, base + OFF_BL);
#pragma unroll
                for (int mt = 0; mt < 4; mt++) {
                    mma16816(acc[mt][np * 2 + 0], ah[mt], bh[0], bh[1]);
                    mma16816(acc[mt][np * 2 + 0], ah[mt], bl[0], bl[1]);
                    mma16816(acc[mt][np * 2 + 0], al[mt], bh[0], bh[1]);
                    mma16816(acc[mt][np * 2 + 1], ah[mt], bh[2], bh[3]);
                    mma16816(acc[mt][np * 2 + 1], ah[mt], bl[2], bl[3]);
                    mma16816(acc[mt][np * 2 + 1], al[mt], bh[2], bh[3]);
                }
            }
        }
        __syncthreads();
    }
#undef LOAD_STAGE

    // epilogue
    const int g  = lane >> 2;
    const int tq = lane & 3;
    const int rB = rowBase + wr * 64;
    const int cB = colBase + wc * 32;

#pragma unroll
    for (int mt = 0; mt < 4; mt++) {
#pragma unroll
        for (int nt = 0; nt < 4; nt++) {
            const int row = rB + mt * 16 + g;
            const int col = cB + nt * 8 + tq * 2;
            float b0 = 0.f, b1 = 0.f;
            if (EPI >= 1) { b0 = bias[col]; b1 = bias[col + 1]; }
            float v0 = acc[mt][nt][0] + b0;
            float v1 = acc[mt][nt][1] + b1;
            float v2 = acc[mt][nt][2] + b0;
            float v3 = acc[mt][nt][3] + b1;
            if (EPI == 2) {
                v0 = 0.5f * v0 * (1.0f + erff(v0 * 0.7071067811865475f));
                v1 = 0.5f * v1 * (1.0f + erff(v1 * 0.7071067811865475f));
                v2 = 0.5f * v2 * (1.0f + erff(v2 * 0.7071067811865475f));
                v3 = 0.5f * v3 * (1.0f + erff(v3 * 0.7071067811865475f));
            }
            if (EPI == 3) { v0 *= 0.125f; v1 *= 0.125f; v2 *= 0.125f; v3 *= 0.125f; }
            if (OUT == 0) {
                *(float2*)&Cf[(size_t)row * N + col]       = make_float2(v0, v1);
                *(float2*)&Cf[(size_t)(row + 8) * N + col] = make_float2(v2, v3);
            } else {
                uint32_t ph, pl;
                split2(v0, v1, ph, pl);
                *(uint32_t*)&Ch[(size_t)row * N + col] = ph;
                *(uint32_t*)&Cl[(size_t)row * N + col] = pl;
                split2(v2, v3, ph, pl);
                *(uint32_t*)&Ch[(size_t)(row + 8) * N + col] = ph;
                *(uint32_t*)&Cl[(size_t)(row + 8) * N + col] = pl;
            }
        }
    }
}

// ---------------------------------------------------------------------------
// Tensor-core causal flash attention; inputs pre-split bf16 hi/lo (Q scaled).
// Grid: (S/64, H, B). Block 128 = 4 warps x 16 query rows.
// ---------------------------------------------------------------------------
#define KPAD 72

__global__ __launch_bounds__(128) void attn_tc_kernel(
    const ushort_t* __restrict__ Qh, const ushort_t* __restrict__ Ql,
    const ushort_t* __restrict__ Kh, const ushort_t* __restrict__ Kl,
    const ushort_t* __restrict__ Vh, const ushort_t* __restrict__ Vl,
    ushort_t* __restrict__ Oh, ushort_t* __restrict__ Ol)
{
    __shared__ ushort_t sKh[64 * KPAD];
    __shared__ ushort_t sKl[64 * KPAD];
    __shared__ ushort_t sVh[64 * KPAD];
    __shared__ ushort_t sVl[64 * KPAD];

    const int qb = blockIdx.x;
    const int h  = blockIdx.y;
    const int b  = blockIdx.z;
    const int t  = threadIdx.x;
    const int lane = t & 31;
    const int warp = t >> 5;
    const int q0 = qb << 6;

    const int g  = lane >> 2;
    const int tq = lane & 3;

    // loader: 2 threads/row, 32 bf16 (4x16B) each
    const int lr = t >> 1;
    const int lc = (t & 1) << 5;
    const int lm = (lane & 15) * KPAD + (lane >> 4) * 8;

    // ---- Stage Q, preload fragments ----
    {
        const size_t gb = (size_t)(b * SEQLEN + q0 + lr) * DMODEL + h * DHEAD + lc;
#pragma unroll
        for (int u = 0; u < 4; u++) {
            *(uint4*)&sKh[lr * KPAD + lc + u * 8] = *(const uint4*)(Qh + gb + u * 8);
            *(uint4*)&sKl[lr * KPAD + lc + u * 8] = *(const uint4*)(Ql + gb + u * 8);
        }
    }
    __syncthreads();

    uint32_t qfh[4][4], qfl[4][4];
#pragma unroll
    for (int kc = 0; kc < 4; kc++) {
        const int base = (warp * 16) * KPAD + kc * 16 + lm;
        ldsm_x4(qfh[kc], smem_u32(&sKh[base]));
        ldsm_x4(qfl[kc], smem_u32(&sKl[base]));
    }
    __syncthreads();

    float m0 = -1e30f, m1 = -1e30f, l0 = 0.f, l1 = 0.f;
    float o[8][4];
#pragma unroll
    for (int j = 0; j < 8; j++)
#pragma unroll
        for (int q = 0; q < 4; q++) o[j][q] = 0.f;

    for (int jb = 0; jb <= qb; jb++) {
        const int j0 = jb << 6;
        {
            const size_t gb = (size_t)(b * SEQLEN + j0 + lr) * DMODEL + h * DHEAD + lc;
#pragma unroll
            for (int u = 0; u < 4; u++) {
                *(uint4*)&sKh[lr * KPAD + lc + u * 8] = *(const uint4*)(Kh + gb + u * 8);
                *(uint4*)&sKl[lr * KPAD + lc + u * 8] = *(const uint4*)(Kl + gb + u * 8);
                *(uint4*)&sVh[lr * KPAD + lc + u * 8] = *(const uint4*)(Vh + gb + u * 8);
                *(uint4*)&sVl[lr * KPAD + lc + u * 8] = *(const uint4*)(Vl + gb + u * 8);
            }
        }
        __syncthreads();

        // S = Q K^T
        float s[8][4];
#pragma unroll
        for (int j = 0; j < 8; j++)
#pragma unroll
            for (int q = 0; q < 4; q++) s[j][q] = 0.f;

#pragma unroll
        for (int kc = 0; kc < 4; kc++) {
#pragma unroll
            for (int kt = 0; kt < 4; kt++) {
                uint32_t kbh[4], kbl[4];
                const int base = (kt * 16) * KPAD + kc * 16 + lm;
                ldsm_x4(kbh, smem_u32(&sKh[base]));
                ldsm_x4(kbl, smem_u32(&sKl[base]));
                mma16816(s[kt * 2 + 0], qfh[kc], kbh[0], kbh[2]);
                mma16816(s[kt * 2 + 0], qfh[kc], kbl[0], kbl[2]);
                mma16816(s[kt * 2 + 0], qfl[kc], kbh[0], kbh[2]);
                mma16816(s[kt * 2 + 1], qfh[kc], kbh[1], kbh[3]);
                mma16816(s[kt * 2 + 1], qfh[kc], kbl[1], kbl[3]);
                mma16816(s[kt * 2 + 1], qfl[kc], kbh[1], kbh[3]);
            }
        }

        if (jb == qb) {
            const int r0 = warp * 16 + g;
            const int r1 = r0 + 8;
#pragma unroll
            for (int j = 0; j < 8; j++) {
                const int c0 = j * 8 + tq * 2;
                if (c0 > r0)     s[j][0] = -1e30f;
                if (c0 + 1 > r0) s[j][1] = -1e30f;
                if (c0 > r1)     s[j][2] = -1e30f;
                if (c0 + 1 > r1) s[j][3] = -1e30f;
            }
        }

        float rm0 = -1e30f, rm1 = -1e30f;
#pragma unroll
        for (int j = 0; j < 8; j++) {
            rm0 = fmaxf(rm0, fmaxf(s[j][0], s[j][1]));
            rm1 = fmaxf(rm1, fmaxf(s[j][2], s[j][3]));
        }
        rm0 = fmaxf(rm0, __shfl_xor_sync(0xffffffffu, rm0, 1));
        rm0 = fmaxf(rm0, __shfl_xor_sync(0xffffffffu, rm0, 2));
        rm1 = fmaxf(rm1, __shfl_xor_sync(0xffffffffu, rm1, 1));
        rm1 = fmaxf(rm1, __shfl_xor_sync(0xffffffffu, rm1, 2));
        const float nm0 = fmaxf(m0, rm0);
        const float nm1 = fmaxf(m1, rm1);

        float rs0 = 0.f, rs1 = 0.f;
#pragma unroll
        for (int j = 0; j < 8; j++) {
            s[j][0] = __expf(s[j][0] - nm0);
            s[j][1] = __expf(s[j][1] - nm0);
            s[j][2] = __expf(s[j][2] - nm1);
            s[j][3] = __expf(s[j][3] - nm1);
            rs0 += s[j][0] + s[j][1];
            rs1 += s[j][2] + s[j][3];
        }
        rs0 += __shfl_xor_sync(0xffffffffu, rs0, 1);
        rs0 += __shfl_xor_sync(0xffffffffu, rs0, 2);
        rs1 += __shfl_xor_sync(0xffffffffu, rs1, 1);
        rs1 += __shfl_xor_sync(0xffffffffu, rs1, 2);

        const float sc0 = __expf(m0 - nm0);
        const float sc1 = __expf(m1 - nm1);
        l0 = l0 * sc0 + rs0;  m0 = nm0;
        l1 = l1 * sc1 + rs1;  m1 = nm1;
#pragma unroll
        for (int j = 0; j < 8; j++) {
            o[j][0] *= sc0; o[j][1] *= sc0;
            o[j][2] *= sc1; o[j][3] *= sc1;
        }

        // O += P V
#pragma unroll
        for (int kc = 0; kc < 4; kc++) {
            uint32_t pah[4], pal[4];
            split2(s[2 * kc + 0][0], s[2 * kc + 0][1], pah[0], pal[0]);
            split2(s[2 * kc + 0][2], s[2 * kc + 0][3], pah[1], pal[1]);
            split2(s[2 * kc + 1][0], s[2 * kc + 1][1], pah[2], pal[2]);
            split2(s[2 * kc + 1][2], s[2 * kc + 1][3], pah[3], pal[3]);
#pragma unroll
            for (int dt = 0; dt < 4; dt++) {
                uint32_t vbh[4], vbl[4];
                const int base = (kc * 16) * KPAD + dt * 16 + lm;
                ldsm_x4t(vbh, smem_u32(&sVh[base]));
                ldsm_x4t(vbl, smem_u32(&sVl[base]));
                mma16816(o[dt * 2 + 0], pah, vbh[0], vbh[1]);
                mma16816(o[dt * 2 + 0], pah, vbl[0], vbl[1]);
                mma16816(o[dt * 2 + 0], pal, vbh[0], vbh[1]);
                mma16816(o[dt * 2 + 1], pah, vbh[2], vbh[3]);
                mma16816(o[dt * 2 + 1], pah, vbl[2], vbl[3]);
                mma16816(o[dt * 2 + 1], pal, vbh[2], vbh[3]);
            }
        }
        __syncthreads();
    }

    // write ctx split
    const float inv0 = 1.0f / l0;
    const float inv1 = 1.0f / l1;
    const int row0 = q0 + warp * 16 + g;
#pragma unroll
    for (int j = 0; j < 8; j++) {
        const int col = h * DHEAD + j * 8 + tq * 2;
        uint32_t ph, pl;
        split2(o[j][0] * inv0, o[j][1] * inv0, ph, pl);
        *(uint32_t*)&Oh[(size_t)(b * SEQLEN + row0) * DMODEL + col] = ph;
        *(uint32_t*)&Ol[(size_t)(b * SEQLEN + row0) * DMODEL + col] = pl;
        split2(o[j][2] * inv1, o[j][3] * inv1, ph, pl);
        *(uint32_t*)&Oh[(size_t)(b * SEQLEN + row0 + 8) * DMODEL + col] = ph;
        *(uint32_t*)&Ol[(size_t)(b * SEQLEN + row0 + 8) * DMODEL + col] = pl;
    }
}

// ---------------------------------------------------------------------------
// out = xres + LN(t)*g + b;  optionally also write (hi,lo) split of out.
// ---------------------------------------------------------------------------
template <bool SPLIT>
__global__ __launch_bounds__(256) void ln_res_kernel(
    const float* __restrict__ xres, const float* __restrict__ tin,
    const float* __restrict__ gam, const float* __restrict__ bet,
    float* __restrict__ out, ushort_t* __restrict__ outh, ushort_t* __restrict__ outl)
{
    const int row = blockIdx.x;
    const int tid = threadIdx.x;
    const float* tr = tin + (size_t)row * DMODEL;

    __shared__ float red[256];
    __shared__ float s_mu, s_rstd;

    float sum = 0.f, sq = 0.f;
    for (int c = tid; c < DMODEL; c += 256) {
        float v = tr[c];
        sum += v;
        sq  += v * v;
    }
    red[tid] = sum;
    __syncthreads();
    for (int s = 128; s > 0; s >>= 1) {
        if (tid < s) red[tid] += red[tid + s];
        __syncthreads();
    }
    if (tid == 0) s_mu = red[0] * (1.0f / DMODEL);
    __syncthreads();
    red[tid] = sq;
    __syncthreads();
    for (int s = 128; s > 0; s >>= 1) {
        if (tid < s) red[tid] += red[tid + s];
        __syncthreads();
    }
    if (tid == 0) {
        float mu  = s_mu;
        float var = red[0] * (1.0f / DMODEL) - mu * mu;
        s_rstd = rsqrtf(var + 1e-5f);
    }
    __syncthreads();

    const float mu = s_mu, rstd = s_rstd;
    for (int c = tid; c < DMODEL; c += 256) {
        float v = xres[(size_t)row * DMODEL + c] + (tr[c] - mu) * rstd * gam[c] + bet[c];
        out[(size_t)row * DMODEL + c] = v;
        if (SPLIT) {
            __nv_bfloat16 bh = __float2bfloat16(v);
            __nv_bfloat16 bl = __float2bfloat16(v - __bfloat162float(bh));
            outh[(size_t)row * DMODEL + c] = __bfloat16_as_ushort(bh);
            outl[(size_t)row * DMODEL + c] = __bfloat16_as_ushort(bl);
        }
    }
}

// ---------------------------------------------------------------------------
extern "C" void kernel_launch(void* const* d_in, const int* in_sizes, int n_in,
                              void* d_out, int out_size)
{
    const float* x    = (const float*)d_in[0];
    const float* wq   = (const float*)d_in[1];
    const float* bq   = (const float*)d_in[2];
    const float* wk   = (const float*)d_in[3];
    const float* bk   = (const float*)d_in[4];
    const float* wv   = (const float*)d_in[5];
    const float* bv   = (const float*)d_in[6];
    const float* wo   = (const float*)d_in[7];
    const float* ln1g = (const float*)d_in[8];
    const float* ln1b = (const float*)d_in[9];
    const float* w1   = (const float*)d_in[10];
    const float* b1   = (const float*)d_in[11];
    const float* w2   = (const float*)d_in[12];
    const float* ln2g = (const float*)d_in[13];
    const float* ln2b = (const float*)d_in[14];
    float* out = (float*)d_out;

#define SYM(T, name, sym) T* name; { void* p_; cudaGetSymbolAddress(&p_, sym); name = (T*)p_; }
    SYM(ushort_t, xh, g_xh)   SYM(ushort_t, xl, g_xl)
    SYM(ushort_t, Qh, g_Qh)   SYM(ushort_t, Ql, g_Ql)
    SYM(ushort_t, Kh, g_Kh)   SYM(ushort_t, Kl, g_Kl)
    SYM(ushort_t, Vh, g_Vh)   SYM(ushort_t, Vl, g_Vl)
    SYM(ushort_t, ctxh, g_ctxh) SYM(ushort_t, ctxl, g_ctxl)
    SYM(ushort_t, x1h, g_x1h) SYM(ushort_t, x1l, g_x1l)
    SYM(ushort_t, hh, g_hh)   SYM(ushort_t, hl, g_hl)
    SYM(float, x1f, g_x1)     SYM(float, tmp, g_tmp)
    SYM(ushort_t, wqh, g_wqh) SYM(ushort_t, wql, g_wql)
    SYM(ushort_t, wkh, g_wkh) SYM(ushort_t, wkl, g_wkl)
    SYM(ushort_t, wvh, g_wvh) SYM(ushort_t, wvl, g_wvl)
    SYM(ushort_t, woh, g_woh) SYM(ushort_t, wol, g_wol)
    SYM(ushort_t, w1h, g_w1h) SYM(ushort_t, w1l, g_w1l)
    SYM(ushort_t, w2h, g_w2h) SYM(ushort_t, w2l, g_w2l)
#undef SYM

    // dynamic smem opt-in (idempotent)
    static bool attr_done = false;
    if (!attr_done) {
        cudaFuncSetAttribute(gemm_pipe<0, 0>, cudaFuncAttributeMaxDynamicSharedMemorySize, GEMM_SMEM);
        cudaFuncSetAttribute(gemm_pipe<0, 1>, cudaFuncAttributeMaxDynamicSharedMemorySize, GEMM_SMEM);
        cudaFuncSetAttribute(gemm_pipe<1, 1>, cudaFuncAttributeMaxDynamicSharedMemorySize, GEMM_SMEM);
        cudaFuncSetAttribute(gemm_pipe<2, 1>, cudaFuncAttributeMaxDynamicSharedMemorySize, GEMM_SMEM);
        cudaFuncSetAttribute(gemm_pipe<3, 1>, cudaFuncAttributeMaxDynamicSharedMemorySize, GEMM_SMEM);
        attr_done = true;
    }

    // 0) splits: x + all weights
    split_kernel<<<TOK * DMODEL / 1024, 256>>>((const float4*)x,  (uint2*)xh,  (uint2*)xl);
    split_kernel<<<DMODEL * DMODEL / 1024, 256>>>((const float4*)wq, (uint2*)wqh, (uint2*)wql);
    split_kernel<<<DMODEL * DMODEL / 1024, 256>>>((const float4*)wk, (uint2*)wkh, (uint2*)wkl);
    split_kernel<<<DMODEL * DMODEL / 1024, 256>>>((const float4*)wv, (uint2*)wvh, (uint2*)wvl);
    split_kernel<<<DMODEL * DMODEL / 1024, 256>>>((const float4*)wo, (uint2*)woh, (uint2*)wol);
    split_kernel<<<DMODEL * DHID / 1024, 256>>>((const float4*)w1, (uint2*)w1h, (uint2*)w1l);
    split_kernel<<<DHID * DMODEL / 1024, 256>>>((const float4*)w2, (uint2*)w2h, (uint2*)w2l);

    // 1) QKV projections (Q pre-scaled by 1/8)
    gemm_pipe<3, 1><<<dim3(8, 32), 256, GEMM_SMEM>>>(xh, xl, wqh, wql, bq, nullptr, Qh, Ql, TOK, DMODEL, DMODEL);
    gemm_pipe<1, 1><<<dim3(8, 32), 256, GEMM_SMEM>>>(xh, xl, wkh, wkl, bk, nullptr, Kh, Kl, TOK, DMODEL, DMODEL);
    gemm_pipe<1, 1><<<dim3(8, 32), 256, GEMM_SMEM>>>(xh, xl, wvh, wvl, bv, nullptr, Vh, Vl, TOK, DMODEL, DMODEL);

    // 2) attention
    attn_tc_kernel<<<dim3(SEQLEN / 64, NHEADS, 2), 128>>>(Qh, Ql, Kh, Kl, Vh, Vl, ctxh, ctxl);

    // 3) Wo projection -> tmp (fp32)
    gemm_pipe<0, 0><<<dim3(8, 32), 256, GEMM_SMEM>>>(ctxh, ctxl, woh, wol, nullptr, tmp, nullptr, nullptr, TOK, DMODEL, DMODEL);

    // 4) x1 = x + LN1(tmp), also split
    ln_res_kernel<true><<<TOK, 256>>>(x, tmp, ln1g, ln1b, x1f, x1h, x1l);

    // 5) h = gelu(x1 @ w1 + b1), split out
    gemm_pipe<2, 1><<<dim3(32, 32), 256, GEMM_SMEM>>>(x1h, x1l, w1h, w1l, b1, nullptr, hh, hl, TOK, DMODEL, DHID);

    // 6) tmp = h @ w2
    gemm_pipe<0, 0><<<dim3(8, 32), 256, GEMM_SMEM>>>(hh, hl, w2h, w2l, nullptr, tmp, nullptr, nullptr, TOK, DHID, DMODEL);

    // 7) out = x1 + LN2(tmp)
    ln_res_kernel<false><<<TOK, 256>>>(x1f, tmp, ln2g, ln2b, out, nullptr, nullptr);
}